// round 3
// baseline (speedup 1.0000x reference)
#include <cuda_runtime.h>
#include <math.h>

#define D_MODEL 1024
#define D_HID   256
#define N_EXP   64
#define NTOK    16384   // 4 * 4096

// Scratch for the hidden activations (allowed: __device__ global array)
__device__ float g_H[(size_t)NTOK * D_HID];

// ---------------- packed fp32x2 helpers (Blackwell FFMA2 path) ----------------
__device__ __forceinline__ unsigned long long pack2(float lo, float hi) {
    unsigned long long r;
    asm("mov.b64 %0, {%1, %2};" : "=l"(r) : "f"(lo), "f"(hi));
    return r;
}
__device__ __forceinline__ void ffma2(unsigned long long& d,
                                      unsigned long long a,
                                      unsigned long long b) {
    asm("fma.rn.f32x2 %0, %1, %2, %0;" : "+l"(d) : "l"(a), "l"(b));
}
__device__ __forceinline__ float2 unpack2(unsigned long long v) {
    float2 f;
    asm("mov.b64 {%0, %1}, %2;" : "=f"(f.x), "=f"(f.y) : "l"(v));
    return f;
}

// =============================================================================
// Kernel 1: H = tanh(X @ W1 + b1)
//   X: [NTOK, 1024], W1: [1024, 256], H: [NTOK, 256]
//   CTA: 256 threads, tile BM=64 tokens x BN=256 (full hidden), BK=16.
//   Per-thread micro-tile 8x8, accumulated as 8x4 f32x2 pairs (FFMA2).
// =============================================================================
__global__ __launch_bounds__(256, 2)
void gemm1_kernel(const float* __restrict__ X,
                  const float* __restrict__ W1,
                  const float* __restrict__ b1) {
    __shared__ float As[16][64];    // A tile, transposed: As[k][m]
    __shared__ float Bs[16][256];   // B tile: Bs[k][n]

    const int tid = threadIdx.x;
    const int m0  = blockIdx.x * 64;

    // compute-thread mapping: tx -> N (32 x 8 cols), ty -> M (8 x 8 rows)
    const int tx = tid & 31;
    const int ty = tid >> 5;

    // A-load mapping: 64 rows x 16 cols, one float4 per thread
    const int arow = tid >> 2;          // 0..63
    const int ac4  = (tid & 3) * 4;     // 0,4,8,12
    // B-load mapping: 16 rows x 256 cols, four float4 per thread
    const int brow = tid >> 4;          // 0..15
    const int bc   = (tid & 15) * 4;    // 0..60

    const float* Xrow = X + (size_t)(m0 + arow) * D_MODEL;

    unsigned long long acc[8][4];
#pragma unroll
    for (int i = 0; i < 8; i++)
#pragma unroll
        for (int j = 0; j < 4; j++) acc[i][j] = 0ull;

    for (int kt = 0; kt < D_MODEL; kt += 16) {
        // prefetch global tiles into registers
        float4 av = *(const float4*)(Xrow + kt + ac4);
        float4 bv[4];
#pragma unroll
        for (int j = 0; j < 4; j++)
            bv[j] = *(const float4*)(W1 + (size_t)(kt + brow) * D_HID + bc + j * 64);

        __syncthreads();  // previous tile fully consumed
        As[ac4 + 0][arow] = av.x;
        As[ac4 + 1][arow] = av.y;
        As[ac4 + 2][arow] = av.z;
        As[ac4 + 3][arow] = av.w;
#pragma unroll
        for (int j = 0; j < 4; j++)
            *(float4*)&Bs[brow][bc + j * 64] = bv[j];
        __syncthreads();

#pragma unroll
        for (int k = 0; k < 16; k++) {
            float4 b0 = *(const float4*)&Bs[k][tx * 4];
            float4 b1v = *(const float4*)&Bs[k][128 + tx * 4];
            unsigned long long bb[4];
            bb[0] = pack2(b0.x, b0.y);
            bb[1] = pack2(b0.z, b0.w);
            bb[2] = pack2(b1v.x, b1v.y);
            bb[3] = pack2(b1v.z, b1v.w);

            float4 a0 = *(const float4*)&As[k][ty * 8];
            float4 a1 = *(const float4*)&As[k][ty * 8 + 4];
            float am[8] = {a0.x, a0.y, a0.z, a0.w, a1.x, a1.y, a1.z, a1.w};
#pragma unroll
            for (int i = 0; i < 8; i++) {
                unsigned long long aa = pack2(am[i], am[i]);
                ffma2(acc[i][0], aa, bb[0]);
                ffma2(acc[i][1], aa, bb[1]);
                ffma2(acc[i][2], aa, bb[2]);
                ffma2(acc[i][3], aa, bb[3]);
            }
        }
    }

    // epilogue: + b1, tanh, store to scratch
    float4 bias0 = *(const float4*)(b1 + tx * 4);
    float4 bias1 = *(const float4*)(b1 + 128 + tx * 4);
#pragma unroll
    for (int i = 0; i < 8; i++) {
        float2 v0 = unpack2(acc[i][0]);
        float2 v1 = unpack2(acc[i][1]);
        float2 v2 = unpack2(acc[i][2]);
        float2 v3 = unpack2(acc[i][3]);
        float4 o0, o1;
        o0.x = tanhf(v0.x + bias0.x);
        o0.y = tanhf(v0.y + bias0.y);
        o0.z = tanhf(v1.x + bias0.z);
        o0.w = tanhf(v1.y + bias0.w);
        o1.x = tanhf(v2.x + bias1.x);
        o1.y = tanhf(v2.y + bias1.y);
        o1.z = tanhf(v3.x + bias1.z);
        o1.w = tanhf(v3.y + bias1.w);
        const size_t m = (size_t)(m0 + ty * 8 + i);
        *(float4*)(g_H + m * D_HID + tx * 4)       = o0;
        *(float4*)(g_H + m * D_HID + 128 + tx * 4) = o1;
    }
}

// =============================================================================
// Kernel 2: logits = H @ W2 + b2; top-2 + softmax; dense gate scatter.
//   CTA: 256 threads, 64 tokens. Micro-tile 4x4 (ty: 16x4 rows, tx: 16x4 cols).
//   W2 (64 KB) stays L1-resident via __ldg broadcast (no smem copy needed).
// =============================================================================
__global__ __launch_bounds__(256, 2)
void gemm2_topk_kernel(const float* __restrict__ W2,
                       const float* __restrict__ b2,
                       float* __restrict__ out_gates,
                       float* __restrict__ out_logits) {
    __shared__ float Hs[16][64];     // H tile, transposed: Hs[k][m]
    __shared__ float Ls[64][68];     // logits tile (padded, float4-aligned rows)

    const int tid = threadIdx.x;
    const int m0  = blockIdx.x * 64;

    const int tx = tid & 15;   // N: 16 x 4 = 64 experts
    const int ty = tid >> 4;   // M: 16 x 4 = 64 tokens

    const int arow = tid >> 2;        // 0..63
    const int ac4  = (tid & 3) * 4;   // 0,4,8,12

    float acc[4][4];
#pragma unroll
    for (int i = 0; i < 4; i++)
#pragma unroll
        for (int j = 0; j < 4; j++) acc[i][j] = 0.0f;

    for (int kt = 0; kt < D_HID; kt += 16) {
        float4 hv = *(const float4*)(g_H + (size_t)(m0 + arow) * D_HID + kt + ac4);
        __syncthreads();
        Hs[ac4 + 0][arow] = hv.x;
        Hs[ac4 + 1][arow] = hv.y;
        Hs[ac4 + 2][arow] = hv.z;
        Hs[ac4 + 3][arow] = hv.w;
        __syncthreads();

#pragma unroll
        for (int k = 0; k < 16; k++) {
            float4 b = __ldg((const float4*)(W2 + (size_t)(kt + k) * N_EXP + tx * 4));
            float4 a = *(const float4*)&Hs[k][ty * 4];
            float am[4] = {a.x, a.y, a.z, a.w};
#pragma unroll
            for (int i = 0; i < 4; i++) {
                acc[i][0] = fmaf(am[i], b.x, acc[i][0]);
                acc[i][1] = fmaf(am[i], b.y, acc[i][1]);
                acc[i][2] = fmaf(am[i], b.z, acc[i][2]);
                acc[i][3] = fmaf(am[i], b.w, acc[i][3]);
            }
        }
    }

    // + b2, stage logits tile in smem
    float4 bias = *(const float4*)(b2 + tx * 4);
#pragma unroll
    for (int i = 0; i < 4; i++) {
        Ls[ty * 4 + i][tx * 4 + 0] = acc[i][0] + bias.x;
        Ls[ty * 4 + i][tx * 4 + 1] = acc[i][1] + bias.y;
        Ls[ty * 4 + i][tx * 4 + 2] = acc[i][2] + bias.z;
        Ls[ty * 4 + i][tx * 4 + 3] = acc[i][3] + bias.w;
    }
    __syncthreads();

    // per-token top-2 + softmax-of-2 + dense scatter (threads 0..63)
    if (tid < 64) {
        const int m = tid;
        float v1 = -INFINITY, v2 = -INFINITY;
        int i1 = -1, i2 = -1;
#pragma unroll
        for (int e = 0; e < N_EXP; e++) {
            float v = Ls[m][e];
            if (v > v1) { v2 = v1; i2 = i1; v1 = v; i1 = e; }
            else if (v > v2) { v2 = v; i2 = e; }
        }
        float e2  = expf(v2 - v1);          // <= 1
        float inv = 1.0f / (1.0f + e2);
        float g1 = inv, g2 = e2 * inv;

        const size_t base = (size_t)(m0 + m) * N_EXP;
#pragma unroll
        for (int e = 0; e < N_EXP; e += 4) {
            float4 lv = *(const float4*)&Ls[m][e];
            float4 gv;
            gv.x = (e + 0 == i1) ? g1 : ((e + 0 == i2) ? g2 : 0.0f);
            gv.y = (e + 1 == i1) ? g1 : ((e + 1 == i2) ? g2 : 0.0f);
            gv.z = (e + 2 == i1) ? g1 : ((e + 2 == i2) ? g2 : 0.0f);
            gv.w = (e + 3 == i1) ? g1 : ((e + 3 == i2) ? g2 : 0.0f);
            *(float4*)(out_gates  + base + e) = gv;
            *(float4*)(out_logits + base + e) = lv;
        }
    }
}

// =============================================================================
extern "C" void kernel_launch(void* const* d_in, const int* in_sizes, int n_in,
                              void* d_out, int out_size) {
    const float* x  = (const float*)d_in[0];   // [4,4096,1024]
    const float* W1 = (const float*)d_in[1];   // [1024,256]
    const float* b1 = (const float*)d_in[2];   // [256]
    const float* W2 = (const float*)d_in[3];   // [256,64]
    const float* b2 = (const float*)d_in[4];   // [64]

    float* out        = (float*)d_out;
    float* out_gates  = out;                     // first tuple element
    float* out_logits = out + (size_t)out_size / 2;  // second tuple element

    gemm1_kernel<<<NTOK / 64, 256>>>(x, W1, b1);
    gemm2_topk_kernel<<<NTOK / 64, 256>>>(W2, b2, out_gates, out_logits);
}